// round 13
// baseline (speedup 1.0000x reference)
#include <cuda_runtime.h>
#include <stdint.h>

// SpikeFP32Floor, round 13: follow the CTA-grain gradient. 1024-thread
// blocks (R12 win) x 4 quads/thread as two pipelined pairs -> 4096 CTAs
// (half of R12). MLP_p1 = 2; pair-1 loads issued before pair-0 stores.
// Bit logic identical to all passing rounds (bit-exact).
//
// Input: 2048*1024 fp32 values, each unpacked MSB-first into 32 floats
// (0.0/1.0). Output: same unpacking of floor(value):
//   e >= 150 -> bits unchanged; 127<=e<150 -> truncate, exact fp32 -1.0f if
//   negative with fractional bits; e < 127 -> sign ? bits(-1.0f) : +0.
//
// Per 32-quad batch: lane L loads float4 #(base+L); batch covers 512B = 4
// fp32 values. group g = L/8 picks the value, slot s = L%8 picks MSB-first
// bit offsets 4s..4s+3. Nibble -> position 28-4s -> OR-tree over the 8-lane
// group (shfl_xor 1,2,4). floor_bits warp-uniform per group. Unpack via
// multiply bit-spread; one STG.128 per quad.

__device__ __forceinline__ unsigned quad_nib(float4 v) {
    // 1.0f = 0x3F800000 (bit 29 set), 0.0f = 0.
    unsigned n;
    n  = (__float_as_uint(v.x) >> 26) & 8u;   // offset 4s   -> nib bit 3
    n |= (__float_as_uint(v.y) >> 27) & 4u;   // offset 4s+1 -> nib bit 2
    n |= (__float_as_uint(v.z) >> 28) & 2u;   // offset 4s+2 -> nib bit 1
    n |= (__float_as_uint(v.w) >> 29) & 1u;   // offset 4s+3 -> nib bit 0
    return n;
}

__device__ __forceinline__ unsigned floor_bits(unsigned u) {
    unsigned sgn = u & 0x80000000u;
    unsigned e   = (u >> 23) & 0xFFu;
    int d = 150 - (int)e;
    unsigned shc  = (unsigned)max(0, min(d, 23));
    unsigned mask = (1u << shc) - 1u;
    unsigned t    = u & ~mask;
    bool hasfrac  = (u & mask) != 0u;
    unsigned tm1  = __float_as_uint(__uint_as_float(t) - 1.0f); // exact here
    unsigned r    = (sgn && hasfrac) ? tm1 : t;
    if (e < 127u) r = sgn ? 0xBF800000u : 0u;
    return r;
}

__device__ __forceinline__ float4 unpack_nib(unsigned r, unsigned sh) {
    unsigned nib = (r >> sh) & 0xFu;
    unsigned sp  = (nib * 0x00204081u) & 0x01010101u;  // bit k -> byte k LSB
    float4 o;
    o.x = __uint_as_float((0u - ((sp >> 24) & 1u)) & 0x3F800000u);
    o.y = __uint_as_float((0u - ((sp >> 16) & 1u)) & 0x3F800000u);
    o.z = __uint_as_float((0u - ((sp >>  8) & 1u)) & 0x3F800000u);
    o.w = __uint_as_float((0u - ( sp        & 1u)) & 0x3F800000u);
    return o;
}

__device__ __forceinline__ unsigned or_tree8(unsigned w) {
    w |= __shfl_xor_sync(0xFFFFFFFFu, w, 1);
    w |= __shfl_xor_sync(0xFFFFFFFFu, w, 2);
    w |= __shfl_xor_sync(0xFFFFFFFFu, w, 4);
    return w;
}

__global__ void __launch_bounds__(1024)
spike_floor_v14(const float4* __restrict__ x, float4* __restrict__ out,
                unsigned int nquads)
{
    unsigned tid  = blockIdx.x * blockDim.x + threadIdx.x;
    unsigned lane = threadIdx.x & 31u;
    unsigned warp = tid >> 5;

    size_t base = (size_t)warp * 128u;          // 128 quads/warp (4/thread)
    if (base + 128u > (size_t)nquads) return;   // warp-uniform guard

    size_t q0 = base + lane;
    unsigned sh = 28u - 4u * (lane & 7u);

    // ---- pair 0 (MLP_p1 = 2) ----
    float4 a = __ldg(&x[q0]);
    float4 b = __ldg(&x[q0 + 32u]);

    unsigned wa = or_tree8(quad_nib(a) << sh);
    unsigned wb = or_tree8(quad_nib(b) << sh);

    float4 oa = unpack_nib(floor_bits(wa), sh);
    float4 ob = unpack_nib(floor_bits(wb), sh);

    // ---- pair 1 loads before pair-0 stores (load/store overlap) ----
    float4 c = __ldg(&x[q0 + 64u]);
    float4 d = __ldg(&x[q0 + 96u]);

    out[q0]       = oa;
    out[q0 + 32u] = ob;

    unsigned wc = or_tree8(quad_nib(c) << sh);
    unsigned wd = or_tree8(quad_nib(d) << sh);

    float4 oc = unpack_nib(floor_bits(wc), sh);
    float4 od = unpack_nib(floor_bits(wd), sh);

    out[q0 + 64u] = oc;
    out[q0 + 96u] = od;
}

extern "C" void kernel_launch(void* const* d_in, const int* in_sizes, int n_in,
                              void* d_out, int out_size)
{
    const float4* x   = (const float4*)d_in[0];
    float4*       out = (float4*)d_out;

    unsigned n_elems = (unsigned)in_sizes[0];   // 2048*1024*32 floats
    unsigned nquads  = n_elems >> 2;            // float4 count
    unsigned threads_total = nquads >> 2;       // 4 quads per thread

    const int threads = 1024;
    unsigned blocks = (threads_total + threads - 1) / threads;

    spike_floor_v14<<<blocks, threads>>>(x, out, nquads);
}

// round 14
// speedup vs baseline: 1.0251x; 1.0251x over previous
#include <cuda_runtime.h>
#include <stdint.h>

// SpikeFP32Floor, round 14: rigor re-bench of v13 (claimed best, 80.64us)
// verbatim — R12 vs R13 showed identical ncu kernel-dur (74.0us) but 1.8us
// bench spread, so the block-size "win" needs reproduction before standing.
//
// 1024-thread blocks, 2 float4 quads/thread, MLP_p1 = 2, shfl OR-tree,
// branchless bit-level floor, multiply bit-spread unpack.
//
// Input: 2048*1024 fp32 values, each unpacked MSB-first into 32 floats
// (0.0/1.0). Output: same unpacking of floor(value), bit-exact:
//   e >= 150 -> bits unchanged; 127<=e<150 -> truncate, exact fp32 -1.0f if
//   negative with fractional bits; e < 127 -> sign ? bits(-1.0f) : +0.
//
// Per 32-quad batch: lane L loads float4 #(base+L); batch covers 512B = 4
// fp32 values. group g = L/8 picks the value, slot s = L%8 picks MSB-first
// bit offsets 4s..4s+3. Nibble -> position 28-4s -> OR-tree over the 8-lane
// group (shfl_xor 1,2,4). floor_bits warp-uniform per group. Unpack via
// multiply bit-spread; one STG.128 per quad.

__device__ __forceinline__ unsigned quad_nib(float4 v) {
    // 1.0f = 0x3F800000 (bit 29 set), 0.0f = 0.
    unsigned n;
    n  = (__float_as_uint(v.x) >> 26) & 8u;   // offset 4s   -> nib bit 3
    n |= (__float_as_uint(v.y) >> 27) & 4u;   // offset 4s+1 -> nib bit 2
    n |= (__float_as_uint(v.z) >> 28) & 2u;   // offset 4s+2 -> nib bit 1
    n |= (__float_as_uint(v.w) >> 29) & 1u;   // offset 4s+3 -> nib bit 0
    return n;
}

__device__ __forceinline__ unsigned floor_bits(unsigned u) {
    unsigned sgn = u & 0x80000000u;
    unsigned e   = (u >> 23) & 0xFFu;
    int d = 150 - (int)e;
    unsigned shc  = (unsigned)max(0, min(d, 23));
    unsigned mask = (1u << shc) - 1u;
    unsigned t    = u & ~mask;
    bool hasfrac  = (u & mask) != 0u;
    unsigned tm1  = __float_as_uint(__uint_as_float(t) - 1.0f); // exact here
    unsigned r    = (sgn && hasfrac) ? tm1 : t;
    if (e < 127u) r = sgn ? 0xBF800000u : 0u;
    return r;
}

__device__ __forceinline__ float4 unpack_nib(unsigned r, unsigned sh) {
    unsigned nib = (r >> sh) & 0xFu;
    unsigned sp  = (nib * 0x00204081u) & 0x01010101u;  // bit k -> byte k LSB
    float4 o;
    o.x = __uint_as_float((0u - ((sp >> 24) & 1u)) & 0x3F800000u);
    o.y = __uint_as_float((0u - ((sp >> 16) & 1u)) & 0x3F800000u);
    o.z = __uint_as_float((0u - ((sp >>  8) & 1u)) & 0x3F800000u);
    o.w = __uint_as_float((0u - ( sp        & 1u)) & 0x3F800000u);
    return o;
}

__device__ __forceinline__ unsigned or_tree8(unsigned w) {
    w |= __shfl_xor_sync(0xFFFFFFFFu, w, 1);
    w |= __shfl_xor_sync(0xFFFFFFFFu, w, 2);
    w |= __shfl_xor_sync(0xFFFFFFFFu, w, 4);
    return w;
}

__global__ void __launch_bounds__(1024)
spike_floor_v13r(const float4* __restrict__ x, float4* __restrict__ out,
                 unsigned int nquads)
{
    unsigned tid  = blockIdx.x * blockDim.x + threadIdx.x;
    unsigned lane = threadIdx.x & 31u;
    unsigned warp = tid >> 5;

    size_t base = (size_t)warp * 64u;           // 64 quads/warp (2/thread)
    if (base + 64u > (size_t)nquads) return;    // warp-uniform guard

    size_t q0 = base + lane;
    size_t q1 = q0 + 32u;

    // Front-batched pair (MLP_p1 = 2).
    float4 a = __ldg(&x[q0]);
    float4 b = __ldg(&x[q1]);

    unsigned sh = 28u - 4u * (lane & 7u);

    unsigned wa = or_tree8(quad_nib(a) << sh);
    unsigned wb = or_tree8(quad_nib(b) << sh);

    float4 oa = unpack_nib(floor_bits(wa), sh);
    float4 ob = unpack_nib(floor_bits(wb), sh);

    out[q0] = oa;
    out[q1] = ob;
}

extern "C" void kernel_launch(void* const* d_in, const int* in_sizes, int n_in,
                              void* d_out, int out_size)
{
    const float4* x   = (const float4*)d_in[0];
    float4*       out = (float4*)d_out;

    unsigned n_elems = (unsigned)in_sizes[0];   // 2048*1024*32 floats
    unsigned nquads  = n_elems >> 2;            // float4 count
    unsigned threads_total = nquads >> 1;       // 2 quads per thread

    const int threads = 1024;
    unsigned blocks = (threads_total + threads - 1) / threads;

    spike_floor_v13r<<<blocks, threads>>>(x, out, nquads);
}

// round 15
// speedup vs baseline: 1.0271x; 1.0020x over previous
#include <cuda_runtime.h>
#include <stdint.h>

// SpikeFP32Floor — FINAL KERNEL (v13, confirmed best: 80.38 / 80.64 us,
// DRAM 82.9%, HBM 6.57 TB/s = mixed read+write streaming plateau).
//
// 1024-thread blocks, 2 float4 quads per thread, MLP_p1 = 2, shfl OR-tree,
// branchless bit-level floor, multiply bit-spread unpack.
//
// Input: 2048*1024 fp32 values, each unpacked MSB-first into 32 floats
// (0.0/1.0). Output: same unpacking of floor(value), bit-exact:
//   e >= 150 -> bits unchanged (already integer / inf / nan)
//   127<=e<150 -> clear low (150-e) mantissa bits; if negative with
//                 fractional bits set, exact fp32 t - 1.0f
//   e < 127 -> sign ? bits(-1.0f) : +0
//
// Per 32-quad batch: lane L loads float4 #(base+L); a batch covers 512B =
// 4 fp32 values. group g = L/8 picks the value, slot s = L%8 picks MSB-first
// bit offsets 4s..4s+3. Nibble -> position 28-4s -> OR-tree over the 8-lane
// group (shfl_xor 1,2,4). floor_bits is warp-uniform per group (no
// divergence). Unpack: (nib * 0x00204081) & 0x01010101 puts nib bit k at
// byte k LSB; component = (0 - bit) & 0x3F800000. One STG.128 per quad.
//
// Session evidence (14 rounds): scalar one-warp-per-value 203us ->
// float4 pack/unpack 82us -> launch-shape sweep 80.4us. All SM-side
// variations (REDUX vs shfl, MLP 2/4, sw pipelining, persistence, cache
// policy) measured neutral; kernel is pinned at the HBM roofline with
// 512 MB compulsory traffic.

__device__ __forceinline__ unsigned quad_nib(float4 v) {
    // 1.0f = 0x3F800000 (bit 29 set), 0.0f = 0.
    unsigned n;
    n  = (__float_as_uint(v.x) >> 26) & 8u;   // offset 4s   -> nib bit 3
    n |= (__float_as_uint(v.y) >> 27) & 4u;   // offset 4s+1 -> nib bit 2
    n |= (__float_as_uint(v.z) >> 28) & 2u;   // offset 4s+2 -> nib bit 1
    n |= (__float_as_uint(v.w) >> 29) & 1u;   // offset 4s+3 -> nib bit 0
    return n;
}

__device__ __forceinline__ unsigned floor_bits(unsigned u) {
    unsigned sgn = u & 0x80000000u;
    unsigned e   = (u >> 23) & 0xFFu;
    int d = 150 - (int)e;
    unsigned shc  = (unsigned)max(0, min(d, 23));
    unsigned mask = (1u << shc) - 1u;
    unsigned t    = u & ~mask;
    bool hasfrac  = (u & mask) != 0u;
    unsigned tm1  = __float_as_uint(__uint_as_float(t) - 1.0f); // exact here
    unsigned r    = (sgn && hasfrac) ? tm1 : t;
    if (e < 127u) r = sgn ? 0xBF800000u : 0u;
    return r;
}

__device__ __forceinline__ float4 unpack_nib(unsigned r, unsigned sh) {
    unsigned nib = (r >> sh) & 0xFu;
    unsigned sp  = (nib * 0x00204081u) & 0x01010101u;  // bit k -> byte k LSB
    float4 o;
    o.x = __uint_as_float((0u - ((sp >> 24) & 1u)) & 0x3F800000u);
    o.y = __uint_as_float((0u - ((sp >> 16) & 1u)) & 0x3F800000u);
    o.z = __uint_as_float((0u - ((sp >>  8) & 1u)) & 0x3F800000u);
    o.w = __uint_as_float((0u - ( sp        & 1u)) & 0x3F800000u);
    return o;
}

__device__ __forceinline__ unsigned or_tree8(unsigned w) {
    w |= __shfl_xor_sync(0xFFFFFFFFu, w, 1);
    w |= __shfl_xor_sync(0xFFFFFFFFu, w, 2);
    w |= __shfl_xor_sync(0xFFFFFFFFu, w, 4);
    return w;
}

__global__ void __launch_bounds__(1024)
spike_floor_final(const float4* __restrict__ x, float4* __restrict__ out,
                  unsigned int nquads)
{
    unsigned tid  = blockIdx.x * blockDim.x + threadIdx.x;
    unsigned lane = threadIdx.x & 31u;
    unsigned warp = tid >> 5;

    size_t base = (size_t)warp * 64u;           // 64 quads/warp (2/thread)
    if (base + 64u > (size_t)nquads) return;    // warp-uniform guard

    size_t q0 = base + lane;
    size_t q1 = q0 + 32u;

    // Front-batched pair (MLP_p1 = 2).
    float4 a = __ldg(&x[q0]);
    float4 b = __ldg(&x[q1]);

    unsigned sh = 28u - 4u * (lane & 7u);

    unsigned wa = or_tree8(quad_nib(a) << sh);
    unsigned wb = or_tree8(quad_nib(b) << sh);

    float4 oa = unpack_nib(floor_bits(wa), sh);
    float4 ob = unpack_nib(floor_bits(wb), sh);

    out[q0] = oa;
    out[q1] = ob;
}

extern "C" void kernel_launch(void* const* d_in, const int* in_sizes, int n_in,
                              void* d_out, int out_size)
{
    const float4* x   = (const float4*)d_in[0];
    float4*       out = (float4*)d_out;

    unsigned n_elems = (unsigned)in_sizes[0];   // 2048*1024*32 floats
    unsigned nquads  = n_elems >> 2;            // float4 count
    unsigned threads_total = nquads >> 1;       // 2 quads per thread

    const int threads = 1024;
    unsigned blocks = (threads_total + threads - 1) / threads;

    spike_floor_final<<<blocks, threads>>>(x, out, nquads);
}